// round 16
// baseline (speedup 1.0000x reference)
#include <cuda_runtime.h>
#include <cuda_fp16.h>
#include <cstdint>
#include <cstddef>

#define KT 8192
#define KE 8
#define KH 2048
#define KI 5632

// ---------- device scratch (static, no allocs) ----------
__device__ __align__(256) __half g_X [(size_t)KT*KH];
__device__ __align__(256) __half g_W1[(size_t)KE*KI*KH];
__device__ __align__(256) __half g_W3[(size_t)KE*KI*KH];
__device__ __align__(256) __half g_W2[(size_t)KE*KH*KI];
__device__ __align__(256) __half g_Hb[(size_t)KE*KT*KI];
__device__ int   g_cnt[KE];
__device__ int   g_done[KE];   // per-expert W1/W3 conversion completion counters
__device__ int   g_tok[KE*KT];
__device__ float g_tw [KE*KT];

// ---------- helpers ----------
__device__ __forceinline__ uint32_t smem_u32(const void* p){
    return (uint32_t)__cvta_generic_to_shared(p);
}
__device__ __forceinline__ void cp16(uint32_t dst, const void* src){
    asm volatile("cp.async.cg.shared.global [%0], [%1], 16;" :: "r"(dst), "l"(src));
}
__device__ __forceinline__ void cp_commit(){ asm volatile("cp.async.commit_group;"); }
template<int N> __device__ __forceinline__ void cp_wait(){
    asm volatile("cp.async.wait_group %0;" :: "n"(N));
}
__device__ __forceinline__ void ldsm4(uint32_t* r, uint32_t a){
    asm volatile("ldmatrix.sync.aligned.m8n8.x4.shared.b16 {%0,%1,%2,%3}, [%4];"
                 : "=r"(r[0]),"=r"(r[1]),"=r"(r[2]),"=r"(r[3]) : "r"(a));
}
__device__ __forceinline__ void mma16(float* d, const uint32_t* a, uint32_t b0, uint32_t b1){
    asm volatile("mma.sync.aligned.m16n8k16.row.col.f32.f16.f16.f32 "
                 "{%0,%1,%2,%3}, {%4,%5,%6,%7}, {%8,%9}, {%0,%1,%2,%3};"
                 : "+f"(d[0]),"+f"(d[1]),"+f"(d[2]),"+f"(d[3])
                 : "r"(a[0]),"r"(a[1]),"r"(a[2]),"r"(a[3]),"r"(b0),"r"(b1));
}

// ---------- routing: top-2 + softmax + compaction ----------
__global__ void k_route(const float* __restrict__ lg){
    int t = blockIdx.x*blockDim.x + threadIdx.x;
    if(t>=KT) return;
    float v[KE];
    #pragma unroll
    for(int e=0;e<KE;e++) v[e]=lg[t*KE+e];
    int i0=0;
    #pragma unroll
    for(int e=1;e<KE;e++) if(v[e]>v[i0]) i0=e;
    int i1=-1;
    #pragma unroll
    for(int e=0;e<KE;e++){ if(e==i0) continue; if(i1<0 || v[e]>v[i1]) i1=e; }
    float wa = 1.f/(1.f + __expf(v[i1]-v[i0]));
    float wb = 1.f - wa;
    int s0 = atomicAdd(&g_cnt[i0],1);
    g_tok[i0*KT+s0]=t; g_tw[i0*KT+s0]=wa;
    int s1 = atomicAdd(&g_cnt[i1],1);
    g_tok[i1*KT+s1]=t; g_tw[i1*KT+s1]=wb;
}

// ---------- fp32 -> fp16 conversion of X (+ per-call flag resets) ----------
__global__ void k_cvtx(const float4* __restrict__ s){
    if(blockIdx.x==0 && threadIdx.x<KE){
        g_cnt[threadIdx.x]=0;
        g_done[threadIdx.x]=0;
    }
    __half2* d = (__half2*)g_X;
    int i = blockIdx.x*blockDim.x + threadIdx.x;
    const int n4 = KT*KH/4;
    for(int j=i;j<n4;j+=gridDim.x*blockDim.x){
        float4 a = s[j];
        d[2*j  ] = __floats2half2_rn(a.x,a.y);
        d[2*j+1] = __floats2half2_rn(a.z,a.w);
    }
}

// ---------- GEMM: PHASE 0 = gate/up (silu*up*tw -> g_Hb fp16), N=64 x {W1,W3}
//   1-D grid with bid-ordered segments:
//     [cvt W1/W3 e0][gemm e0 head][cvt W1/W3 e1..7][gemm rest]
//   Every gemm-path block also converts a tiny gidx-strided slice of W2 and
//   zeroes a slice of out BEFORE its W1/W3 spin — this work hides inside
//   tensor-paced blocks (idle LSU/DRAM), not in dedicated slot-stealing blocks.
//   gemm blocks spin on g_done[e] (converters always at lower bids -> no deadlock)
//                  PHASE 1 = down-proj (atomicAdd -> out), N=128 x W2 (3-D grid)
// CTA tile 128(M) x 128(B-rows) x 64(K); 8 warps; 3-stage cp.async
template<int PHASE>
__global__ void __launch_bounds__(256,2) k_gemm(float* __restrict__ out,
                                                const float4* __restrict__ w1src,
                                                const float4* __restrict__ w3src,
                                                const float4* __restrict__ w2src){
    constexpr int KD = (PHASE==0) ? KH : KI;   // GEMM K dim
    constexpr int NB = (PHASE==0) ? 2  : 1;    // number of B matrices
    constexpr int NI = (PHASE==0) ? 4  : 8;    // n-frags (8 cols) per warp per matrix
    constexpr int NT = (PHASE==0) ? 64 : 128;  // N cols per matrix per CTA
    constexpr int KS = KD/64;
    constexpr int AST = 128*64;                // halves per A stage
    constexpr int BST = 128*64;                // halves per B stage (128 rows total)

    const int tid = threadIdx.x;
    int e, m0, n0;

    if(PHASE==0){
        // ---- segment decode (1-D grid) ----
        int bid = blockIdx.x;
        int gidx = -1, cvte = -1, cvtj = 0, cvtB = 0;
        if(bid < 256){ cvte=0; cvtj=bid; cvtB=256; }
        else if(bid < 552){ gidx = bid-256; }
        else if(bid < 1000){ int r=bid-552; cvte=1+r/64; cvtj=r%64; cvtB=64; }
        else { gidx = 296 + (bid-1000); }

        if(cvte >= 0){
            // convert W1[cvte], W3[cvte] fp32 -> fp16, then publish flag
            const float4* s1 = w1src + (size_t)cvte*KI*KH/4;
            const float4* s3 = w3src + (size_t)cvte*KI*KH/4;
            __half2* d1 = (__half2*)(g_W1 + (size_t)cvte*KI*KH);
            __half2* d3 = (__half2*)(g_W3 + (size_t)cvte*KI*KH);
            const int n4 = KI*KH/4;
            for(int j=cvtj*256+tid; j<n4; j+=cvtB*256){
                float4 a = s1[j];
                d1[2*j  ] = __floats2half2_rn(a.x,a.y);
                d1[2*j+1] = __floats2half2_rn(a.z,a.w);
                float4 b = s3[j];
                d3[2*j  ] = __floats2half2_rn(b.x,b.y);
                d3[2*j+1] = __floats2half2_rn(b.z,b.w);
            }
            __syncthreads();
            __threadfence();
            if(tid==0) atomicAdd(&g_done[cvte], 1);
            return;
        }

        // ---- interleaved W2 conversion + output zeroing (gidx-strided slice)
        // gemm0 never reads W2/out, gemm1 launches after -> ordering safe.
        {
            const int base   = gidx*256 + tid;
            const int stride = 45056*256;
            __half2* dw = (__half2*)g_W2;
            const int n4w = KE*KH*KI/4;
            for(int j=base; j<n4w; j+=stride){
                float4 a = w2src[j];
                dw[2*j  ] = __floats2half2_rn(a.x,a.y);
                dw[2*j+1] = __floats2half2_rn(a.z,a.w);
            }
            float4* ov = (float4*)out;
            const int z4 = KT*KH/4;
            float4 zz = make_float4(0.f,0.f,0.f,0.f);
            for(int j=base; j<z4; j+=stride) ov[j]=zz;
        }

        e  = gidx / 5632;
        int rem = gidx % 5632;
        n0 = (rem/64)*64;
        m0 = (rem%64)*128;
    } else {
        e  = blockIdx.z;
        m0 = blockIdx.x*128;
        n0 = blockIdx.y*NT;
    }

    const int cnt = g_cnt[e];
    if(m0 >= cnt) return;

    if(PHASE==0){
        // wait for this expert's W1/W3 conversion (converters at lower bids)
        const int target = (e==0) ? 256 : 64;
        if(tid==0){
            while(*((volatile int*)&g_done[e]) < target) __nanosleep(256);
        }
        __syncthreads();
        __threadfence();
    }

    extern __shared__ __half sm[];
    __half* sA = sm;              // [3][128][64]
    __half* sW = sm + 3*AST;      // [3][128][64]
    __shared__ int   s_tok[128];
    __shared__ float s_tw [128];

    if(tid < 128){
        int r = min(m0+tid, cnt-1);
        s_tok[tid] = g_tok[e*KT + r];
        if(PHASE==0) s_tw[tid] = g_tw[e*KT + r];
    }
    __syncthreads();

    const __half* Wp0 = (PHASE==0) ? (g_W1 + (size_t)e*KI*KH) : (g_W2 + (size_t)e*KH*KI);
    const __half* Wp1 = g_W3 + (size_t)e*KI*KH;

    auto load_stage = [&](int L){
        const int st = L%3, k0 = L*64;
        uint32_t baseA = smem_u32(sA + st*AST);
        #pragma unroll
        for(int it=0; it<4; it++){
            int c = it*256 + tid;
            int row = c>>3, cb = c&7;
            int sc = cb ^ (row&7);
            const __half* src = (PHASE==0)
                ? (g_X  + (size_t)s_tok[row]*KH + k0 + cb*8)
                : (g_Hb + (size_t)(e*KT + m0 + row)*KI + k0 + cb*8);
            cp16(baseA + row*128 + sc*16, src);
        }
        uint32_t baseW = smem_u32(sW + st*BST);
        #pragma unroll
        for(int it=0; it<4; it++){             // 128 B rows total
            int c = it*256 + tid;
            int row = c>>3, cb = c&7;
            int sc = cb ^ (row&7);
            const __half* W = (PHASE==0 && row>=64) ? Wp1 : Wp0;
            int wrow = (PHASE==0) ? (row&63) : row;
            cp16(baseW + row*128 + sc*16, W + (size_t)(n0+wrow)*KD + k0 + cb*8);
        }
        cp_commit();
    };

    float acc[NB][2][NI][4];
    #pragma unroll
    for(int b=0;b<NB;b++)
        #pragma unroll
        for(int mi=0;mi<2;mi++)
            #pragma unroll
            for(int ni=0;ni<NI;ni++)
                #pragma unroll
                for(int k=0;k<4;k++) acc[b][mi][ni][k]=0.f;

    const int lane = tid & 31, warp = tid >> 5;
    const int wm = (warp>>1)*32, wn = (warp&1)*(NI*8);

    auto compute = [&](int st){
        uint32_t baseA = smem_u32(sA + st*AST);
        uint32_t baseW = smem_u32(sW + st*BST);
        #pragma unroll
        for(int km=0; km<4; km++){
            uint32_t a[2][4];
            #pragma unroll
            for(int mi=0;mi<2;mi++){
                int row = wm + mi*16 + (lane&15);
                int c   = km*2 + (lane>>4);
                int sc  = c ^ (row&7);
                ldsm4(a[mi], baseA + row*128 + sc*16);
            }
            #pragma unroll
            for(int b=0;b<NB;b++){
                uint32_t bw = baseW + b*64*128;
                uint32_t bf[NI][2];
                #pragma unroll
                for(int nb=0;nb<NI/2;nb++){
                    int row = wn + nb*16 + (lane&15);
                    int c   = km*2 + (lane>>4);
                    int sc  = c ^ (row&7);
                    uint32_t r[4];
                    ldsm4(r, bw + row*128 + sc*16);
                    bf[nb*2  ][0]=r[0]; bf[nb*2+1][0]=r[1];
                    bf[nb*2  ][1]=r[2]; bf[nb*2+1][1]=r[3];
                }
                #pragma unroll
                for(int mi=0;mi<2;mi++)
                    #pragma unroll
                    for(int ni=0;ni<NI;ni++)
                        mma16(acc[b][mi][ni], a[mi], bf[ni][0], bf[ni][1]);
            }
        }
    };

    load_stage(0); load_stage(1);
    #pragma unroll 3
    for(int ks=0; ks<KS; ks++){
        if(ks+1<KS) cp_wait<1>(); else cp_wait<0>();
        __syncthreads();
        if(ks+2<KS) load_stage(ks+2);   // overlapped with compute below
        compute(ks%3);
    }

    // epilogue
    #pragma unroll
    for(int mi=0;mi<2;mi++){
        #pragma unroll
        for(int hh=0;hh<2;hh++){
            int row = wm + mi*16 + (lane>>2) + hh*8;
            int r   = m0 + row;
            if(PHASE==0){
                float tw = (r < cnt) ? s_tw[row] : 0.f;
                __half* dst = g_Hb + (size_t)(e*KT + r)*KI + n0;
                #pragma unroll
                for(int ni=0;ni<NI;ni++){
                    int col = wn + ni*8 + (lane&3)*2;
                    float gg0 = acc[0][mi][ni][hh*2], gg1 = acc[0][mi][ni][hh*2+1];
                    float uu0 = acc[NB-1][mi][ni][hh*2], uu1 = acc[NB-1][mi][ni][hh*2+1];
                    float h0 = tw * (gg0/(1.f+__expf(-gg0))) * uu0;
                    float h1 = tw * (gg1/(1.f+__expf(-gg1))) * uu1;
                    *(__half2*)(dst + col) = __floats2half2_rn(h0,h1);
                }
            } else {
                if(r < cnt){
                    int t = s_tok[row];
                    float* dst = out + (size_t)t*KH + n0;
                    #pragma unroll
                    for(int ni=0;ni<NI;ni++){
                        int col = wn + ni*8 + (lane&3)*2;
                        atomicAdd(dst + col    , acc[0][mi][ni][hh*2  ]);
                        atomicAdd(dst + col + 1, acc[0][mi][ni][hh*2+1]);
                    }
                }
            }
        }
    }
}

// ---------- launch ----------
extern "C" void kernel_launch(void* const* d_in, const int* in_sizes, int n_in,
                              void* d_out, int out_size){
    const float* hs = (const float*)d_in[0];
    const float* lg = (const float*)d_in[1];
    const float* w1 = (const float*)d_in[2];
    const float* w2 = (const float*)d_in[3];
    const float* w3 = (const float*)d_in[4];
    float* out = (float*)d_out;

    const int DS = 3*(128*64 + 128*64)*2;  // 98304 B (both phases)
    cudaFuncSetAttribute(k_gemm<0>, cudaFuncAttributeMaxDynamicSharedMemorySize, DS);
    cudaFuncSetAttribute(k_gemm<1>, cudaFuncAttributeMaxDynamicSharedMemorySize, DS);

    k_cvtx <<<2048, 256>>>((const float4*)hs);   // 1 (X cvt + zero g_cnt/g_done)
    k_route<<<KT/256, 256>>>(lg);                // 2

    // 1-D grid: 256 cvt-e0 + 296 gemm-e0 head + 448 cvt-e1..7 + remaining gemm
    // (W2 cvt + out zeroing interleaved inside the gemm blocks themselves)
    const int G0 = 256 + 448 + 8*5632;           // 45760
    k_gemm<0><<<G0, 256, DS>>>(out, (const float4*)w1, (const float4*)w3,
                               (const float4*)w2);                      // 3

    dim3 gB(KT/128, KH/128, KE);  // m fastest
    k_gemm<1><<<gB, 256, DS>>>(out, nullptr, nullptr, nullptr);         // 4
}